// round 17
// baseline (speedup 1.0000x reference)
#include <cuda_runtime.h>
#include <cuda_fp16.h>
#include <math.h>
#include <stdint.h>

#define NN 1024
#define HH 64

__device__ float    g_A[NN * HH];     // z_c @ W1[:64]  (fp32)
__device__ float    g_B[NN * HH];     // z_d @ W1[64:] + b1 (fp32)
__device__ uint32_t g_Bh[NN * 32];    // half2-packed B
__device__ float    g_T1[NN * NN];
__device__ double   g_acc;
__device__ int      g_cnt;

// ---------------------------------------------------------------------------
// fp16-accumulate MMA: C/D are 2 regs (half2 x2): {(c0,c1),(c2,c3)}
#define MMA16816H(c, a0, a1, a2, a3, b0, b1)                                  \
    asm("mma.sync.aligned.m16n8k16.row.col.f16.f16.f16.f16 "                  \
        "{%0,%1}, {%2,%3,%4,%5}, {%6,%7}, {%0,%1};"                           \
        : "+r"((c)[0]), "+r"((c)[1])                                          \
        : "r"(a0), "r"(a1), "r"(a2), "r"(a3), "r"(b0), "r"(b1))

__device__ __forceinline__ uint32_t pack_h2(float e0, float e1) {  // lo=e0, hi=e1
    uint32_t r;
    asm("cvt.rn.f16x2.f32 %0, %1, %2;" : "=r"(r) : "f"(e1), "f"(e0));
    return r;
}
// relu(a + b) in packed fp16
__device__ __forceinline__ uint32_t frag_h2(uint32_t a, uint32_t b) {
    __half2 r = __hmax2(__hadd2(*(__half2*)&a, *(__half2*)&b),
                        __half2half2(__ushort_as_half(0)));
    return *(uint32_t*)&r;
}

// ---------------------------------------------------------------------------
// Kernel 1: precompute A and B. 32 blocks; src tile staged in smem; this
// thread's W column preloaded into registers (64 coalesced LDG, high MLP).
// ---------------------------------------------------------------------------
__global__ __launch_bounds__(256, 2) void prep_kernel(
    const float* __restrict__ zc, const float* __restrict__ zd,
    const float* __restrict__ W1, const float* __restrict__ b1) {
    __shared__ float4 sS[1024];          // 64 rows x 64 cols of src
    const int tid = threadIdx.x;
    const int which = blockIdx.y;
    const int r0 = blockIdx.x * 64;

    if (blockIdx.x == 0 && which == 0 && tid == 0) { g_acc = 0.0; g_cnt = 0; }

    const float* src = which ? zd : zc;
    const float* w   = W1 + (which ? 64 * HH : 0);

    // stage src tile (coalesced float4)
    const float4* src4 = (const float4*)(src + (size_t)r0 * 64);
#pragma unroll
    for (int t = tid; t < 1024; t += 256) sS[t] = src4[t];

    // preload this thread's W column (64 coalesced loads, all independent)
    const int col = tid & 63;
    const int rg  = tid >> 6;            // 0..3 (16 rows each)
    float wreg[64];
#pragma unroll
    for (int k = 0; k < 64; ++k) wreg[k] = w[k * HH + col];

    const float bias = which ? b1[col] : 0.0f;
    __syncthreads();

#pragma unroll
    for (int r = 0; r < 16; ++r) {
        const int row = rg * 16 + r;
        const float4* srow = &sS[row * 16];
        float s0 = bias, s1 = 0.f, s2 = 0.f, s3 = 0.f;
#pragma unroll
        for (int k4 = 0; k4 < 16; ++k4) {
            float4 sv = srow[k4];
            s0 = fmaf(sv.x, wreg[4 * k4 + 0], s0);
            s1 = fmaf(sv.y, wreg[4 * k4 + 1], s1);
            s2 = fmaf(sv.z, wreg[4 * k4 + 2], s2);
            s3 = fmaf(sv.w, wreg[4 * k4 + 3], s3);
        }
        float s = (s0 + s1) + (s2 + s3);
        const int grow = r0 + row;
        if (which) {
            g_B[grow * HH + col] = s;
            float s_hi = __shfl_down_sync(0xffffffffu, s, 1);
            if ((col & 1) == 0)
                g_Bh[grow * 32 + (col >> 1)] = pack_h2(s, s_hi);
        } else {
            g_A[grow * HH + col] = s;
        }
    }
}

// ---------------------------------------------------------------------------
// Kernel 2: pairwise MLP via HMMA (fp16 x fp16, fp16 acc), occ 3.
// R17: cross-iteration software pipeline — double-buffered accumulators;
// MMAs for iteration i+1 are issued BEFORE the epilogue of iteration i, so
// the tensor pipe stays fed through the epilogue bubble.
// ---------------------------------------------------------------------------
#define JSTRIDE 27   // CTAs per j-block; grid = 16 * 27 = 432 (1 wave at occ 3)

#define MMA_BODY(acc, I)                                                      \
    do {                                                                      \
        uint32_t bi_[8];                                                      \
        _Pragma("unroll")                                                     \
        for (int q = 0; q < 8; ++q) bi_[q] = nbi[q];                          \
        if ((I) + JSTRIDE < NN) {                                             \
            const uint32_t* Bn_ = g_Bh + (size_t)((I) + JSTRIDE) * 32;        \
            _Pragma("unroll")                                                 \
            for (int ks = 0; ks < 4; ++ks) {                                  \
                nbi[2 * ks]     = Bn_[8 * ks + tid4];                         \
                nbi[2 * ks + 1] = Bn_[8 * ks + 4 + tid4];                     \
            }                                                                 \
        }                                                                     \
        _Pragma("unroll")                                                     \
        for (int nt = 0; nt < 8; ++nt) { acc[nt][0] = 0u; acc[nt][1] = 0u; }  \
        _Pragma("unroll")                                                     \
        for (int ks = 0; ks < 4; ++ks) {                                      \
            const int k2_ = 8 * ks + tid4;                                    \
            uint32_t a0_ = frag_h2(sA2[k2_ * 72 + m0],           bi_[2 * ks]);        \
            uint32_t a1_ = frag_h2(sA2[k2_ * 72 + m0 + 8],       bi_[2 * ks]);        \
            uint32_t a2_ = frag_h2(sA2[(k2_ + 4) * 72 + m0],     bi_[2 * ks + 1]);    \
            uint32_t a3_ = frag_h2(sA2[(k2_ + 4) * 72 + m0 + 8], bi_[2 * ks + 1]);    \
            _Pragma("unroll")                                                 \
            for (int nt = 0; nt < 8; ++nt)                                    \
                MMA16816H(acc[nt], a0_, a1_, a2_, a3_,                        \
                          Bf[ks][nt][0], Bf[ks][nt][1]);                      \
        }                                                                     \
    } while (0)

#define EPI_BODY(acc, I)                                                      \
    do {                                                                      \
        float sA0_ = 0.f, sA1_ = 0.f;                                         \
        _Pragma("unroll")                                                     \
        for (int nt = 0; nt < 8; ++nt) {                                      \
            float2 c01_ = __half22float2(*(const __half2*)&acc[nt][0]);       \
            float2 c23_ = __half22float2(*(const __half2*)&acc[nt][1]);       \
            float d0_ = c01_.x + b2r[nt].x;                                   \
            float d1_ = c01_.y + b2r[nt].y;                                   \
            float d2_ = c23_.x + b2r[nt].x;                                   \
            float d3_ = c23_.y + b2r[nt].y;                                   \
            sA0_ = fmaf(fmaxf(d0_, 0.f), wor[nt].x, sA0_);                    \
            sA0_ = fmaf(fmaxf(d1_, 0.f), wor[nt].y, sA0_);                    \
            sA1_ = fmaf(fmaxf(d2_, 0.f), wor[nt].x, sA1_);                    \
            sA1_ = fmaf(fmaxf(d3_, 0.f), wor[nt].y, sA1_);                    \
        }                                                                     \
        sA0_ += __shfl_xor_sync(0xffffffffu, sA0_, 1);                        \
        sA0_ += __shfl_xor_sync(0xffffffffu, sA0_, 2);                        \
        sA1_ += __shfl_xor_sync(0xffffffffu, sA1_, 1);                        \
        sA1_ += __shfl_xor_sync(0xffffffffu, sA1_, 2);                        \
        if (tid4 == 0) {                                                      \
            g_T1[(size_t)(I) * NN + j0 + m0]     = sA0_ + bo;                 \
            g_T1[(size_t)(I) * NN + j0 + m0 + 8] = sA1_ + bo;                 \
        }                                                                     \
    } while (0)

__global__ __launch_bounds__(128, 3) void pair_mma_kernel(
    const float* __restrict__ W2, const float* __restrict__ b2,
    const float* __restrict__ Wo, const float* __restrict__ bo_p) {
    __shared__ uint32_t sA2[32 * 72];   // [k2][m] half2(A[m][2k2],A[m][2k2+1])

    const int tid  = threadIdx.x;
    const int lane = tid & 31;
    const int wid  = tid >> 5;
    const int gid  = lane >> 2;      // 0..7
    const int tid4 = lane & 3;       // 0..3

    const int jb  = blockIdx.x / JSTRIDE;    // 0..15
    const int s0i = blockIdx.x % JSTRIDE;    // starting i
    const int j0  = jb * 64;

    // ---- stage A block as packed half2, transposed ----
    for (int idx = tid; idx < 2048; idx += 128) {
        int m = idx >> 5, k2 = idx & 31;
        float2 f = *(const float2*)(g_A + (size_t)(j0 + m) * 64 + 2 * k2);
        sA2[k2 * 72 + m] = pack_h2(f.x, f.y);
    }

    // ---- preload W2 fragments (fp16) into registers ----
    uint32_t Bf[4][8][2];
#pragma unroll
    for (int ks = 0; ks < 4; ++ks) {
#pragma unroll
        for (int nt = 0; nt < 8; ++nt) {
            int k0 = 16 * ks + 2 * tid4;
            int n  = 8 * nt + gid;
            Bf[ks][nt][0] = pack_h2(W2[(k0 + 0) * HH + n], W2[(k0 + 1) * HH + n]);
            Bf[ks][nt][1] = pack_h2(W2[(k0 + 8) * HH + n], W2[(k0 + 9) * HH + n]);
        }
    }

    // ---- per-thread epilogue constants ----
    float2 b2r[8], wor[8];
#pragma unroll
    for (int nt = 0; nt < 8; ++nt) {
        int n = 8 * nt + 2 * tid4;
        b2r[nt] = make_float2(b2[n], b2[n + 1]);
        wor[nt] = make_float2(Wo[n], Wo[n + 1]);
    }
    const float bo = bo_p[0];
    const int m0 = wid * 16 + gid;

    __syncthreads();                 // sA2 ready (only barrier in kernel)

    // ---- prime the Bi pipeline ----
    uint32_t nbi[8];
    {
        const uint32_t* Bi = g_Bh + (size_t)s0i * 32;
#pragma unroll
        for (int ks = 0; ks < 4; ++ks) {
            nbi[2 * ks]     = Bi[8 * ks + tid4];
            nbi[2 * ks + 1] = Bi[8 * ks + 4 + tid4];
        }
    }

    // ---- software-pipelined main loop (MMA(i+1) before EPI(i)) ----
    uint32_t accA[8][2], accB[8][2];
    int i = s0i;
    MMA_BODY(accA, i);
    for (;;) {
        int iB = i + JSTRIDE;
        if (iB >= NN) { EPI_BODY(accA, i); break; }
        MMA_BODY(accB, iB);
        EPI_BODY(accA, i);
        int iA = iB + JSTRIDE;
        if (iA >= NN) { EPI_BODY(accB, iB); break; }
        MMA_BODY(accA, iA);
        EPI_BODY(accB, iB);
        i = iA;
    }
}

// ---------------------------------------------------------------------------
// Kernel 3: logsumexp + diagonal + fused final reduction.
// All 8 rows' data prefetched into registers up-front (MLP 8).
// ---------------------------------------------------------------------------
__global__ void lse_kernel(float* out) {
    __shared__ float sm[8], ss[8];
    const int tid = threadIdx.x;
    const int lane = tid & 31, wid = tid >> 5;
    double local = 0.0;

    float4 v[8];
#pragma unroll
    for (int r = 0; r < 8; ++r)
        v[r] = ((const float4*)(g_T1 + (size_t)(blockIdx.x * 8 + r) * NN))[tid];

#pragma unroll 1
    for (int r = 0; r < 8; ++r) {
        const int i = blockIdx.x * 8 + r;

        float m = fmaxf(fmaxf(v[r].x, v[r].y), fmaxf(v[r].z, v[r].w));
#pragma unroll
        for (int o = 16; o > 0; o >>= 1)
            m = fmaxf(m, __shfl_xor_sync(0xffffffffu, m, o));
        if (lane == 0) sm[wid] = m;
        __syncthreads();
        float bm = sm[0];
#pragma unroll
        for (int w = 1; w < 8; ++w) bm = fmaxf(bm, sm[w]);

        float s = __expf(v[r].x - bm) + __expf(v[r].y - bm) +
                  __expf(v[r].z - bm) + __expf(v[r].w - bm);
#pragma unroll
        for (int o = 16; o > 0; o >>= 1)
            s += __shfl_xor_sync(0xffffffffu, s, o);
        if (lane == 0) ss[wid] = s;
        __syncthreads();

        if (tid == 0) {
            float tot = ss[0] + ss[1] + ss[2] + ss[3] +
                        ss[4] + ss[5] + ss[6] + ss[7];
            local += (double)g_T1[(size_t)i * NN + i]
                   - ((double)bm + log((double)tot));
        }
        __syncthreads();
    }

    if (tid == 0) {
        atomicAdd(&g_acc, local);
        __threadfence();
        if (atomicAdd(&g_cnt, 1) == 127) {
            double acc = atomicAdd(&g_acc, 0.0);
            out[0] = (float)(acc / NN + log((double)NN));
        }
    }
}

// ---------------------------------------------------------------------------
extern "C" void kernel_launch(void* const* d_in, const int* in_sizes, int n_in,
                              void* d_out, int out_size) {
    const float* z_c = (const float*)d_in[0];
    const float* z_d = (const float*)d_in[1];
    const float* W1  = (const float*)d_in[2];
    const float* b1  = (const float*)d_in[3];
    const float* W2  = (const float*)d_in[4];
    const float* b2  = (const float*)d_in[5];
    const float* Wo  = (const float*)d_in[6];
    const float* bo  = (const float*)d_in[7];
    float* out = (float*)d_out;

    prep_kernel<<<dim3(16, 2), 256>>>(z_c, z_d, W1, b1);
    pair_mma_kernel<<<16 * JSTRIDE, 128>>>(W2, b2, Wo, bo);
    lse_kernel<<<128, 256>>>(out);
}